// round 10
// baseline (speedup 1.0000x reference)
#include <cuda_runtime.h>

// GCN_52871047413869 — 2-layer GCN + global mean pool + FC, fp32.
//   x [100000,6], edge_index [2,1600000] (int32 OR int64 — detected at runtime),
//   batch [100000] sorted (int32 OR int64), W1 [6,64], b1[64], W2 [64,128],
//   b2[128], Wfc [128,2], bfc[2] -> out [1000,2] float32

#define N_NODES  100000
#define N_EDGES  1600000
#define N_GRAPHS 1000
#define F0 6
#define F1 64
#define F2 128

// ---- scratch (device globals: allocations are banned) ----
__device__ __align__(16) float g_deg  [N_NODES];
__device__ __align__(16) float g_dinv [N_NODES];
__device__ __align__(16) int   g_src32[N_EDGES];
__device__ __align__(16) int   g_dst32[N_EDGES];
__device__ __align__(16) int   g_bat32[N_NODES];
__device__ __align__(16) float g_norm [N_EDGES];
__device__ __align__(16) float g_h1   [N_NODES * F1];   // x @ W1
__device__ __align__(16) float g_o1   [N_NODES * F1];   // layer-1 agg (pre-relu)
__device__ __align__(16) float g_h2   [N_NODES * F2];   // relu(o1) @ W2
__device__ __align__(16) float g_o2   [N_NODES * F2];   // layer-2 agg (pre-relu)
__device__ __align__(16) float g_pool [N_GRAPHS * F2];
__device__ __align__(16) float g_cnt  [N_GRAPHS];
__device__ int g_edge_is64;
__device__ int g_bat_is64;

// ---------------------------------------------------------------------------
// dtype detection: sample buffers as int64. int32 data packs two indices per
// int64 slot -> values >= 2^32 with overwhelming probability. Sampled slots
// are in-bounds under EITHER dtype (edge: <1.6M slots, batch: <50K slots).
// ---------------------------------------------------------------------------
__global__ void k_detect(const void* ei, const void* bat) {
    if (blockIdx.x | threadIdx.x) return;
    const long long* e = (const long long*)ei;
    int ok = 1;
    for (int j = 0; j < 64; j++) {
        long long v = e[j * 24991];            // < 1.6M
        if (v < 0 || v >= N_NODES) { ok = 0; break; }
    }
    g_edge_is64 = ok;
    const long long* b = (const long long*)bat;
    int ok2 = 1;
    for (int j = 0; j < 64; j++) {
        long long v = b[j * 771];              // < 50K (sorted: skip the 0-prefix)
        if (v < 0 || v >= N_GRAPHS) { ok2 = 0; break; }
    }
    g_bat_is64 = ok2;
}

__device__ __forceinline__ int clampi(int v, int hi) {
    return (unsigned)v < (unsigned)hi ? v : 0;
}

// convert indices to int32 (clamped: structurally prevents wild atomics)
__global__ void k_cvt_edges(const void* ei) {
    int e = blockIdx.x * blockDim.x + threadIdx.x;
    if (e >= N_EDGES) return;
    int s, d;
    if (g_edge_is64) {
        const long long* p = (const long long*)ei;
        s = (int)p[e]; d = (int)p[N_EDGES + e];
    } else {
        const int* p = (const int*)ei;
        s = p[e]; d = p[N_EDGES + e];
    }
    g_src32[e] = clampi(s, N_NODES);
    g_dst32[e] = clampi(d, N_NODES);
}

__global__ void k_cvt_batch(const void* bat) {
    int i = blockIdx.x * blockDim.x + threadIdx.x;
    if (i >= N_NODES) return;
    int g;
    if (g_bat_is64) g = (int)((const long long*)bat)[i];
    else            g = ((const int*)bat)[i];
    g_bat32[i] = clampi(g, N_GRAPHS);
}

// ---------------------------------------------------------------------------
// degree / norm
// ---------------------------------------------------------------------------
__global__ void k_deg_init() {
    int i = blockIdx.x * blockDim.x + threadIdx.x;
    if (i < N_NODES) g_deg[i] = 1.0f;               // self loop
}

__global__ void k_deg_acc() {
    int e = blockIdx.x * blockDim.x + threadIdx.x;
    if (e < N_EDGES) atomicAdd(&g_deg[g_dst32[e]], 1.0f);
}

__global__ void k_dinv() {
    int i = blockIdx.x * blockDim.x + threadIdx.x;
    if (i < N_NODES) g_dinv[i] = rsqrtf(g_deg[i]);  // deg >= 1 always
}

__global__ void k_norm() {
    int e = blockIdx.x * blockDim.x + threadIdx.x;
    if (e < N_EDGES) g_norm[e] = g_dinv[g_src32[e]] * g_dinv[g_dst32[e]];
}

// ---------------------------------------------------------------------------
// layer 1: h1 = x @ W1 ; o1 = b1 + h1 * dinv^2   (self-loop term folded in)
// ---------------------------------------------------------------------------
__global__ void k_h1(const float* __restrict__ x,
                     const float* __restrict__ W1,
                     const float* __restrict__ b1) {
    __shared__ float W1s[F0 * F1];
    __shared__ float b1s[F1];
    for (int t = threadIdx.x; t < F0 * F1; t += blockDim.x) W1s[t] = W1[t];
    for (int t = threadIdx.x; t < F1; t += blockDim.x)       b1s[t] = b1[t];
    __syncthreads();

    int gt = blockIdx.x * blockDim.x + threadIdx.x;
    if (gt >= N_NODES * F1) return;
    int i = gt >> 6;
    int f = gt & 63;

    float acc = 0.f;
    #pragma unroll
    for (int k = 0; k < F0; k++)
        acc = fmaf(x[i * F0 + k], W1s[k * F1 + f], acc);

    g_h1[gt] = acc;
    float di = g_dinv[i];
    g_o1[gt] = b1s[f] + acc * di * di;
}

// ---------------------------------------------------------------------------
// layer-1 edge scatter: o1[dst] += h1[src] * norm ; 16 threads/edge
// ---------------------------------------------------------------------------
__global__ void k_edge1() {
    long long gt = (long long)blockIdx.x * blockDim.x + threadIdx.x;
    if (gt >= (long long)N_EDGES * 16) return;
    int e = (int)(gt >> 4);
    int q = (int)(gt & 15);

    int   src = g_src32[e];
    int   dst = g_dst32[e];
    float nrm = g_norm[e];

    const float4 v = *reinterpret_cast<const float4*>(&g_h1[(size_t)src * F1 + q * 4]);
    float* o = &g_o1[(size_t)dst * F1 + q * 4];
    atomicAdd(o + 0, v.x * nrm);
    atomicAdd(o + 1, v.y * nrm);
    atomicAdd(o + 2, v.z * nrm);
    atomicAdd(o + 3, v.w * nrm);
}

// ---------------------------------------------------------------------------
// layer 2: h2 = relu(o1) @ W2 ; o2 = b2 + h2 * dinv^2
// ---------------------------------------------------------------------------
#define H2_NODES 4
__global__ void __launch_bounds__(128) k_h2(const float* __restrict__ W2,
                                            const float* __restrict__ b2) {
    __shared__ float W2s[F1 * F2];
    __shared__ float xs[H2_NODES][F1];
    for (int t = threadIdx.x; t < F1 * F2; t += 128) W2s[t] = W2[t];
    float bb = b2[threadIdx.x];
    __syncthreads();

    int f = threadIdx.x;
    for (int base = blockIdx.x * H2_NODES; base < N_NODES;
         base += gridDim.x * H2_NODES) {
        #pragma unroll
        for (int t = threadIdx.x; t < H2_NODES * F1; t += 128) {
            int j = t >> 6, k = t & 63;
            xs[j][k] = fmaxf(g_o1[(size_t)(base + j) * F1 + k], 0.f);
        }
        __syncthreads();

        float a0 = 0.f, a1 = 0.f, a2 = 0.f, a3 = 0.f;
        #pragma unroll
        for (int k = 0; k < F1; k++) {
            float w = W2s[k * F2 + f];
            a0 = fmaf(xs[0][k], w, a0);
            a1 = fmaf(xs[1][k], w, a1);
            a2 = fmaf(xs[2][k], w, a2);
            a3 = fmaf(xs[3][k], w, a3);
        }

        float acc[H2_NODES] = {a0, a1, a2, a3};
        #pragma unroll
        for (int j = 0; j < H2_NODES; j++) {
            int node = base + j;
            float di = g_dinv[node];
            g_h2[(size_t)node * F2 + f] = acc[j];
            g_o2[(size_t)node * F2 + f] = bb + acc[j] * di * di;
        }
        __syncthreads();
    }
}

// ---------------------------------------------------------------------------
// layer-2 edge scatter: o2[dst] += h2[src] * norm ; 32 threads/edge
// ---------------------------------------------------------------------------
__global__ void k_edge2() {
    long long gt = (long long)blockIdx.x * blockDim.x + threadIdx.x;
    if (gt >= (long long)N_EDGES * 32) return;
    int e = (int)(gt >> 5);
    int q = (int)(gt & 31);

    int   src = g_src32[e];
    int   dst = g_dst32[e];
    float nrm = g_norm[e];

    const float4 v = *reinterpret_cast<const float4*>(&g_h2[(size_t)src * F2 + q * 4]);
    float* o = &g_o2[(size_t)dst * F2 + q * 4];
    atomicAdd(o + 0, v.x * nrm);
    atomicAdd(o + 1, v.y * nrm);
    atomicAdd(o + 2, v.z * nrm);
    atomicAdd(o + 3, v.w * nrm);
}

// ---------------------------------------------------------------------------
// pooling
// ---------------------------------------------------------------------------
__global__ void k_zero_pool() {
    int i = blockIdx.x * blockDim.x + threadIdx.x;
    if (i < N_GRAPHS * F2) g_pool[i] = 0.f;
    if (i < N_GRAPHS)      g_cnt[i]  = 0.f;
}

__global__ void k_pool() {
    int gt = blockIdx.x * blockDim.x + threadIdx.x;   // (node, quad)
    if (gt >= N_NODES * (F2 / 4)) return;
    int i = gt >> 5;
    int q = gt & 31;
    int g = g_bat32[i];

    const float4 v = *reinterpret_cast<const float4*>(&g_o2[(size_t)i * F2 + q * 4]);
    float* p = &g_pool[g * F2 + q * 4];
    atomicAdd(p + 0, fmaxf(v.x, 0.f));
    atomicAdd(p + 1, fmaxf(v.y, 0.f));
    atomicAdd(p + 2, fmaxf(v.z, 0.f));
    atomicAdd(p + 3, fmaxf(v.w, 0.f));
    if (q == 0) atomicAdd(&g_cnt[g], 1.0f);
}

__global__ void k_fc(const float* __restrict__ Wfc,
                     const float* __restrict__ bfc,
                     float* __restrict__ out) {
    int t = blockIdx.x * blockDim.x + threadIdx.x;
    if (t >= N_GRAPHS * 2) return;
    int g = t >> 1, j = t & 1;
    float s = 0.f;
    #pragma unroll 8
    for (int f = 0; f < F2; f++)
        s = fmaf(g_pool[g * F2 + f], Wfc[f * 2 + j], s);
    out[t] = s / fmaxf(g_cnt[g], 1.0f) + bfc[j];
}

// ---------------------------------------------------------------------------
extern "C" void kernel_launch(void* const* d_in, const int* in_sizes, int n_in,
                              void* d_out, int out_size) {
    // Resolve inputs by UNIQUE element count (immune to ordering assumptions).
    const void *p_x = 0, *p_ei = 0, *p_bat = 0, *p_W1 = 0, *p_b1 = 0,
               *p_W2 = 0, *p_b2 = 0, *p_Wfc = 0, *p_bfc = 0;
    for (int i = 0; i < n_in; i++) {
        switch (in_sizes[i]) {
            case 600000:  p_x   = d_in[i]; break;
            case 3200000: p_ei  = d_in[i]; break;
            case 100000:  p_bat = d_in[i]; break;
            case 384:     p_W1  = d_in[i]; break;
            case 64:      p_b1  = d_in[i]; break;
            case 8192:    p_W2  = d_in[i]; break;
            case 128:     p_b2  = d_in[i]; break;
            case 256:     p_Wfc = d_in[i]; break;
            case 2:       p_bfc = d_in[i]; break;
            default: break;
        }
    }
    const float* x   = (const float*)p_x;
    const float* W1  = (const float*)p_W1;
    const float* b1  = (const float*)p_b1;
    const float* W2  = (const float*)p_W2;
    const float* b2  = (const float*)p_b2;
    const float* Wfc = (const float*)p_Wfc;
    const float* bfc = (const float*)p_bfc;
    float*       out = (float*)d_out;

    const int T = 256;
    const int GB_NODE = (N_NODES + T - 1) / T;
    const int GB_EDGE = (N_EDGES + T - 1) / T;

    k_detect   <<<1, 32>>>(p_ei, p_bat);
    k_cvt_edges<<<GB_EDGE, T>>>(p_ei);
    k_cvt_batch<<<GB_NODE, T>>>(p_bat);

    k_deg_init<<<GB_NODE, T>>>();
    k_deg_acc <<<GB_EDGE, T>>>();
    k_dinv    <<<GB_NODE, T>>>();
    k_norm    <<<GB_EDGE, T>>>();

    k_h1<<<(N_NODES * F1 + T - 1) / T, T>>>(x, W1, b1);

    {
        long long tot = (long long)N_EDGES * 16;
        k_edge1<<<(unsigned)((tot + T - 1) / T), T>>>();
    }

    k_h2<<<2048, 128>>>(W2, b2);

    {
        long long tot = (long long)N_EDGES * 32;
        k_edge2<<<(unsigned)((tot + T - 1) / T), T>>>();
    }

    k_zero_pool<<<(N_GRAPHS * F2 + T - 1) / T, T>>>();
    k_pool<<<(N_NODES * (F2 / 4) + T - 1) / T, T>>>();
    k_fc<<<(N_GRAPHS * 2 + T - 1) / T, T>>>(Wfc, bfc, out);
}

// round 15
// speedup vs baseline: 2.0675x; 2.0675x over previous
#include <cuda_runtime.h>

// GCN_52871047413869 — 2-layer GCN + global mean pool + FC, fp32.
// CSR-gather formulation: zero atomics in the hot aggregation loops.

#define N_NODES  100000
#define N_EDGES  1600000
#define N_GRAPHS 1000
#define F0 6
#define F1 64
#define F2 128
#define SCAN_B 256
#define NBLK   ((N_NODES + SCAN_B - 1) / SCAN_B)   // 391

// ---- scratch (device globals: allocations are banned) ----
__device__ __align__(16) float g_dinv [N_NODES];
__device__ __align__(16) int   g_degI [N_NODES];     // incoming-edge count
__device__ __align__(16) int   g_off  [N_NODES];     // CSR exclusive offsets
__device__ __align__(16) int   g_cur  [N_NODES];     // fill cursors
__device__ __align__(16) int   g_bsum [512];         // scan block sums
__device__ __align__(16) int   g_src32[N_EDGES];
__device__ __align__(16) int   g_dst32[N_EDGES];
__device__ __align__(16) int   g_esrc [N_EDGES];     // CSR: src per slot
__device__ __align__(16) float g_enrm [N_EDGES];     // CSR: norm per slot
__device__ __align__(16) int   g_bat32[N_NODES];
__device__ __align__(16) int   g_bstart[N_GRAPHS];
__device__ __align__(16) int   g_bend  [N_GRAPHS];
__device__ __align__(16) float g_h1   [N_NODES * F1];   // x @ W1
__device__ __align__(16) float g_a1   [N_NODES * F1];   // relu(layer-1 out)
__device__ __align__(16) float g_h2   [N_NODES * F2];   // a1 @ W2
__device__ __align__(16) float g_a2   [N_NODES * F2];   // relu(layer-2 out)
__device__ int g_edge_is64;
__device__ int g_bat_is64;

// ---------------------------------------------------------------------------
// dtype detection (verified working in R10) — sample as int64; int32 data
// packs two indices per slot -> out-of-range values. Sampled slots in-bounds
// under either dtype.
// ---------------------------------------------------------------------------
__global__ void k_detect(const void* ei, const void* bat) {
    if (blockIdx.x | threadIdx.x) return;
    const long long* e = (const long long*)ei;
    int ok = 1;
    for (int j = 0; j < 64; j++) {
        long long v = e[j * 24991];
        if (v < 0 || v >= N_NODES) { ok = 0; break; }
    }
    g_edge_is64 = ok;
    const long long* b = (const long long*)bat;
    int ok2 = 1;
    for (int j = 0; j < 64; j++) {
        long long v = b[j * 771];
        if (v < 0 || v >= N_GRAPHS) { ok2 = 0; break; }
    }
    g_bat_is64 = ok2;
}

__device__ __forceinline__ int clampi(int v, int hi) {
    return (unsigned)v < (unsigned)hi ? v : 0;
}

__global__ void k_cvt_edges(const void* ei) {
    int e = blockIdx.x * blockDim.x + threadIdx.x;
    if (e >= N_EDGES) return;
    int s, d;
    if (g_edge_is64) {
        const long long* p = (const long long*)ei;
        s = (int)p[e]; d = (int)p[N_EDGES + e];
    } else {
        const int* p = (const int*)ei;
        s = p[e]; d = p[N_EDGES + e];
    }
    g_src32[e] = clampi(s, N_NODES);
    g_dst32[e] = clampi(d, N_NODES);
}

__global__ void k_cvt_batch(const void* bat) {
    int i = blockIdx.x * blockDim.x + threadIdx.x;
    if (i >= N_NODES) return;
    int g;
    if (g_bat_is64) g = (int)((const long long*)bat)[i];
    else            g = ((const int*)bat)[i];
    g_bat32[i] = clampi(g, N_GRAPHS);
}

// ---------------------------------------------------------------------------
// CSR build: count -> dinv -> 2-level exclusive scan -> fill
// ---------------------------------------------------------------------------
__global__ void k_zero_deg() {
    int i = blockIdx.x * blockDim.x + threadIdx.x;
    if (i < N_NODES) g_degI[i] = 0;
    if (i < N_GRAPHS) { g_bstart[i] = 0x7FFFFFFF; g_bend[i] = 0; }
}

__global__ void k_count() {
    int e = blockIdx.x * blockDim.x + threadIdx.x;
    if (e < N_EDGES) atomicAdd(&g_degI[g_dst32[e]], 1);
}

__global__ void k_dinv() {
    int i = blockIdx.x * blockDim.x + threadIdx.x;
    if (i < N_NODES) g_dinv[i] = rsqrtf((float)(g_degI[i] + 1));  // +1 self loop
}

__global__ void k_scan1() {                 // per-block exclusive scan + totals
    __shared__ int sh[SCAN_B];
    int i = blockIdx.x * SCAN_B + threadIdx.x;
    int v = (i < N_NODES) ? g_degI[i] : 0;
    sh[threadIdx.x] = v;
    __syncthreads();
    for (int ofs = 1; ofs < SCAN_B; ofs <<= 1) {
        int t = (threadIdx.x >= ofs) ? sh[threadIdx.x - ofs] : 0;
        __syncthreads();
        sh[threadIdx.x] += t;
        __syncthreads();
    }
    if (i < N_NODES) g_off[i] = sh[threadIdx.x] - v;     // exclusive in-block
    if (threadIdx.x == SCAN_B - 1) g_bsum[blockIdx.x] = sh[SCAN_B - 1];
}

__global__ void k_scan2() {                 // scan the 391 block totals
    __shared__ int sh[512];
    int t = threadIdx.x;
    int orig = (t < NBLK) ? g_bsum[t] : 0;
    sh[t] = orig;
    __syncthreads();
    for (int ofs = 1; ofs < 512; ofs <<= 1) {
        int v = (t >= ofs) ? sh[t - ofs] : 0;
        __syncthreads();
        sh[t] += v;
        __syncthreads();
    }
    if (t < NBLK) g_bsum[t] = sh[t] - orig;              // exclusive
}

__global__ void k_scan3() {                 // add block offsets, zero cursors
    int i = blockIdx.x * blockDim.x + threadIdx.x;
    if (i < N_NODES) {
        g_off[i] += g_bsum[i >> 8];         // SCAN_B == 256
        g_cur[i] = 0;
    }
}

__global__ void k_fill() {
    int e = blockIdx.x * blockDim.x + threadIdx.x;
    if (e >= N_EDGES) return;
    int s = g_src32[e];
    int d = g_dst32[e];
    int pos  = atomicAdd(&g_cur[d], 1);
    int slot = g_off[d] + pos;
    g_esrc[slot] = s;
    g_enrm[slot] = g_dinv[s] * g_dinv[d];
}

// ---------------------------------------------------------------------------
// layer 1 dense: h1 = x @ W1
// ---------------------------------------------------------------------------
__global__ void k_h1(const float* __restrict__ x,
                     const float* __restrict__ W1) {
    __shared__ float W1s[F0 * F1];
    for (int t = threadIdx.x; t < F0 * F1; t += blockDim.x) W1s[t] = W1[t];
    __syncthreads();

    int gt = blockIdx.x * blockDim.x + threadIdx.x;
    if (gt >= N_NODES * F1) return;
    int i = gt >> 6;
    int f = gt & 63;

    float acc = 0.f;
    #pragma unroll
    for (int k = 0; k < F0; k++)
        acc = fmaf(x[i * F0 + k], W1s[k * F1 + f], acc);
    g_h1[gt] = acc;
}

// ---------------------------------------------------------------------------
// layer-1 gather: a1[d] = relu(b1 + h1[d]*dinv[d]^2 + sum_e h1[src]*norm)
// 16 lanes per dst, one float4 (4 feats) per lane. Zero atomics.
// ---------------------------------------------------------------------------
__global__ void __launch_bounds__(128) k_gath1(const float* __restrict__ b1) {
    int t = blockIdx.x * blockDim.x + threadIdx.x;
    int d    = t >> 4;
    int lane = t & 15;
    if (d >= N_NODES) return;

    int off = g_off[d];
    int deg = g_degI[d];
    const int fo = lane * 4;

    float4 acc = make_float4(0.f, 0.f, 0.f, 0.f);
    int j = 0;
    for (; j + 2 <= deg; j += 2) {
        int   s0 = g_esrc[off + j],     s1 = g_esrc[off + j + 1];
        float n0 = g_enrm[off + j],     n1 = g_enrm[off + j + 1];
        float4 v0 = *(const float4*)&g_h1[(size_t)s0 * F1 + fo];
        float4 v1 = *(const float4*)&g_h1[(size_t)s1 * F1 + fo];
        acc.x = fmaf(v0.x, n0, fmaf(v1.x, n1, acc.x));
        acc.y = fmaf(v0.y, n0, fmaf(v1.y, n1, acc.y));
        acc.z = fmaf(v0.z, n0, fmaf(v1.z, n1, acc.z));
        acc.w = fmaf(v0.w, n0, fmaf(v1.w, n1, acc.w));
    }
    if (j < deg) {
        int   s0 = g_esrc[off + j];
        float n0 = g_enrm[off + j];
        float4 v0 = *(const float4*)&g_h1[(size_t)s0 * F1 + fo];
        acc.x = fmaf(v0.x, n0, acc.x);
        acc.y = fmaf(v0.y, n0, acc.y);
        acc.z = fmaf(v0.z, n0, acc.z);
        acc.w = fmaf(v0.w, n0, acc.w);
    }

    float di = g_dinv[d];
    float dd = di * di;
    float4 h  = *(const float4*)&g_h1[(size_t)d * F1 + fo];
    float4 bb = *(const float4*)&b1[fo];
    float4 o;
    o.x = fmaxf(bb.x + fmaf(h.x, dd, acc.x), 0.f);
    o.y = fmaxf(bb.y + fmaf(h.y, dd, acc.y), 0.f);
    o.z = fmaxf(bb.z + fmaf(h.z, dd, acc.z), 0.f);
    o.w = fmaxf(bb.w + fmaf(h.w, dd, acc.w), 0.f);
    *(float4*)&g_a1[(size_t)d * F1 + fo] = o;
}

// ---------------------------------------------------------------------------
// layer 2 dense: h2 = a1 @ W2   (a1 is already relu'd)
// ---------------------------------------------------------------------------
#define H2_NODES 4
__global__ void __launch_bounds__(128) k_h2(const float* __restrict__ W2) {
    __shared__ float W2s[F1 * F2];
    __shared__ float xs[H2_NODES][F1];
    for (int t = threadIdx.x; t < F1 * F2; t += 128) W2s[t] = W2[t];
    __syncthreads();

    int f = threadIdx.x;
    for (int base = blockIdx.x * H2_NODES; base < N_NODES;
         base += gridDim.x * H2_NODES) {
        #pragma unroll
        for (int t = threadIdx.x; t < H2_NODES * F1; t += 128) {
            int j = t >> 6, k = t & 63;
            xs[j][k] = g_a1[(size_t)(base + j) * F1 + k];
        }
        __syncthreads();

        float a0 = 0.f, a1v = 0.f, a2v = 0.f, a3v = 0.f;
        #pragma unroll
        for (int k = 0; k < F1; k++) {
            float w = W2s[k * F2 + f];
            a0  = fmaf(xs[0][k], w, a0);
            a1v = fmaf(xs[1][k], w, a1v);
            a2v = fmaf(xs[2][k], w, a2v);
            a3v = fmaf(xs[3][k], w, a3v);
        }
        g_h2[(size_t)(base + 0) * F2 + f] = a0;
        g_h2[(size_t)(base + 1) * F2 + f] = a1v;
        g_h2[(size_t)(base + 2) * F2 + f] = a2v;
        g_h2[(size_t)(base + 3) * F2 + f] = a3v;
        __syncthreads();
    }
}

// ---------------------------------------------------------------------------
// layer-2 gather: a2[d] = relu(b2 + h2[d]*dinv^2 + sum_e h2[src]*norm)
// 32 lanes (one warp) per dst, float4 per lane. Zero atomics.
// ---------------------------------------------------------------------------
__global__ void __launch_bounds__(128) k_gath2(const float* __restrict__ b2) {
    int t = blockIdx.x * blockDim.x + threadIdx.x;
    int d    = t >> 5;
    int lane = t & 31;
    if (d >= N_NODES) return;

    int off = g_off[d];
    int deg = g_degI[d];
    const int fo = lane * 4;

    float4 acc = make_float4(0.f, 0.f, 0.f, 0.f);
    int j = 0;
    for (; j + 2 <= deg; j += 2) {
        int   s0 = g_esrc[off + j],     s1 = g_esrc[off + j + 1];
        float n0 = g_enrm[off + j],     n1 = g_enrm[off + j + 1];
        float4 v0 = *(const float4*)&g_h2[(size_t)s0 * F2 + fo];
        float4 v1 = *(const float4*)&g_h2[(size_t)s1 * F2 + fo];
        acc.x = fmaf(v0.x, n0, fmaf(v1.x, n1, acc.x));
        acc.y = fmaf(v0.y, n0, fmaf(v1.y, n1, acc.y));
        acc.z = fmaf(v0.z, n0, fmaf(v1.z, n1, acc.z));
        acc.w = fmaf(v0.w, n0, fmaf(v1.w, n1, acc.w));
    }
    if (j < deg) {
        int   s0 = g_esrc[off + j];
        float n0 = g_enrm[off + j];
        float4 v0 = *(const float4*)&g_h2[(size_t)s0 * F2 + fo];
        acc.x = fmaf(v0.x, n0, acc.x);
        acc.y = fmaf(v0.y, n0, acc.y);
        acc.z = fmaf(v0.z, n0, acc.z);
        acc.w = fmaf(v0.w, n0, acc.w);
    }

    float di = g_dinv[d];
    float dd = di * di;
    float4 h  = *(const float4*)&g_h2[(size_t)d * F2 + fo];
    float4 bb = *(const float4*)&b2[fo];
    float4 o;
    o.x = fmaxf(bb.x + fmaf(h.x, dd, acc.x), 0.f);
    o.y = fmaxf(bb.y + fmaf(h.y, dd, acc.y), 0.f);
    o.z = fmaxf(bb.z + fmaf(h.z, dd, acc.z), 0.f);
    o.w = fmaxf(bb.w + fmaf(h.w, dd, acc.w), 0.f);
    *(float4*)&g_a2[(size_t)d * F2 + fo] = o;
}

// ---------------------------------------------------------------------------
// pooling + FC fused. batch is sorted -> per-graph contiguous node ranges.
// ---------------------------------------------------------------------------
__global__ void k_bounds() {
    int i = blockIdx.x * blockDim.x + threadIdx.x;
    if (i >= N_NODES) return;
    int g = g_bat32[i];
    atomicMin(&g_bstart[g], i);
    atomicMax(&g_bend[g], i + 1);
}

__global__ void __launch_bounds__(128) k_poolfc(const float* __restrict__ Wfc,
                                                const float* __restrict__ bfc,
                                                float* __restrict__ out) {
    int g = blockIdx.x;
    int s = g_bstart[g], e = g_bend[g];
    int f = threadIdx.x;

    float sum = 0.f;
    for (int i = s; i < e; i++)                 // empty graph: s>e, no iters
        sum += g_a2[(size_t)i * F2 + f];
    float cnt = (e > s) ? (float)(e - s) : 1.0f;
    float pooled = sum / cnt;

    __shared__ float sh0[128], sh1[128];
    sh0[f] = pooled * Wfc[f * 2 + 0];
    sh1[f] = pooled * Wfc[f * 2 + 1];
    __syncthreads();
    for (int ofs = 64; ofs > 0; ofs >>= 1) {
        if (f < ofs) { sh0[f] += sh0[f + ofs]; sh1[f] += sh1[f + ofs]; }
        __syncthreads();
    }
    if (f == 0) {
        out[g * 2 + 0] = sh0[0] + bfc[0];
        out[g * 2 + 1] = sh1[0] + bfc[1];
    }
}

// ---------------------------------------------------------------------------
extern "C" void kernel_launch(void* const* d_in, const int* in_sizes, int n_in,
                              void* d_out, int out_size) {
    // Resolve inputs by UNIQUE element count (verified in R10).
    const void *p_x = 0, *p_ei = 0, *p_bat = 0, *p_W1 = 0, *p_b1 = 0,
               *p_W2 = 0, *p_b2 = 0, *p_Wfc = 0, *p_bfc = 0;
    for (int i = 0; i < n_in; i++) {
        switch (in_sizes[i]) {
            case 600000:  p_x   = d_in[i]; break;
            case 3200000: p_ei  = d_in[i]; break;
            case 100000:  p_bat = d_in[i]; break;
            case 384:     p_W1  = d_in[i]; break;
            case 64:      p_b1  = d_in[i]; break;
            case 8192:    p_W2  = d_in[i]; break;
            case 128:     p_b2  = d_in[i]; break;
            case 256:     p_Wfc = d_in[i]; break;
            case 2:       p_bfc = d_in[i]; break;
            default: break;
        }
    }
    const float* x   = (const float*)p_x;
    const float* W1  = (const float*)p_W1;
    const float* b1  = (const float*)p_b1;
    const float* W2  = (const float*)p_W2;
    const float* b2  = (const float*)p_b2;
    const float* Wfc = (const float*)p_Wfc;
    const float* bfc = (const float*)p_bfc;
    float*       out = (float*)d_out;

    const int T = 256;
    const int GB_NODE = (N_NODES + T - 1) / T;
    const int GB_EDGE = (N_EDGES + T - 1) / T;

    // input parsing (proven)
    k_detect   <<<1, 32>>>(p_ei, p_bat);
    k_cvt_edges<<<GB_EDGE, T>>>(p_ei);
    k_cvt_batch<<<GB_NODE, T>>>(p_bat);

    // CSR build
    k_zero_deg<<<GB_NODE, T>>>();
    k_count   <<<GB_EDGE, T>>>();
    k_dinv    <<<GB_NODE, T>>>();
    k_scan1   <<<NBLK, SCAN_B>>>();
    k_scan2   <<<1, 512>>>();
    k_scan3   <<<GB_NODE, T>>>();
    k_fill    <<<GB_EDGE, T>>>();

    // layer 1
    k_h1   <<<(N_NODES * F1 + T - 1) / T, T>>>(x, W1);
    k_gath1<<<(N_NODES * 16 + 127) / 128, 128>>>(b1);

    // layer 2
    k_h2   <<<2048, 128>>>(W2);
    k_gath2<<<(N_NODES * 32 + 127) / 128, 128>>>(b2);

    // pool + fc
    k_bounds<<<GB_NODE, T>>>();
    k_poolfc<<<N_GRAPHS, 128>>>(Wfc, bfc, out);
}